// round 11
// baseline (speedup 1.0000x reference)
#include <cuda_runtime.h>
#include <cuda_bf16.h>
#include <cstdint>

#define B_ 4
#define S_ 2048
#define DM_ 1024
#define H_ 16
#define DK_ 64
#define M_ (B_ * S_)   // 8192

// Scratch (device globals; allocation-free per harness rules)
__device__ __nv_bfloat16 g_Ahi[M_ * DM_];
__device__ __nv_bfloat16 g_Alo[M_ * DM_];
__device__ __nv_bfloat16 g_Whi[DM_ * DM_];
__device__ __nv_bfloat16 g_Wlo[DM_ * DM_];
__device__ __nv_bfloat16 g_Qhi[B_ * H_ * S_ * DK_];
__device__ __nv_bfloat16 g_Qlo[B_ * H_ * S_ * DK_];
__device__ __nv_bfloat16 g_Khi[B_ * H_ * S_ * DK_];
__device__ __nv_bfloat16 g_Klo[B_ * H_ * S_ * DK_];
__device__ __nv_bfloat16 g_Vhi[B_ * H_ * S_ * DK_];
__device__ __nv_bfloat16 g_Vlo[B_ * H_ * S_ * DK_];

// ===========================================================================
// Base-ISA helpers (valid on sm_103 WITHOUT the 'a' feature set)
// ===========================================================================
__device__ __forceinline__ uint32_t smem_u32(const void* p) {
    uint32_t a;
    asm("{ .reg .u64 t; cvta.to.shared.u64 t, %1; cvt.u32.u64 %0, t; }"
        : "=r"(a) : "l"(p));
    return a;
}
__device__ __forceinline__ void ldsm4(uint32_t* r, uint32_t addr) {
    asm volatile("ldmatrix.sync.aligned.m8n8.x4.shared.b16 {%0,%1,%2,%3}, [%4];"
                 : "=r"(r[0]), "=r"(r[1]), "=r"(r[2]), "=r"(r[3]) : "r"(addr));
}
__device__ __forceinline__ void ldsm4t(uint32_t* r, uint32_t addr) {
    asm volatile("ldmatrix.sync.aligned.m8n8.x4.trans.shared.b16 {%0,%1,%2,%3}, [%4];"
                 : "=r"(r[0]), "=r"(r[1]), "=r"(r[2]), "=r"(r[3]) : "r"(addr));
}
__device__ __forceinline__ void mma_bf16(float* d, const uint32_t* a, const uint32_t* b) {
    asm volatile(
        "mma.sync.aligned.m16n8k16.row.col.f32.bf16.bf16.f32 "
        "{%0,%1,%2,%3}, {%4,%5,%6,%7}, {%8,%9}, {%0,%1,%2,%3};"
        : "+f"(d[0]), "+f"(d[1]), "+f"(d[2]), "+f"(d[3])
        : "r"(a[0]), "r"(a[1]), "r"(a[2]), "r"(a[3]), "r"(b[0]), "r"(b[1]));
}
#define CP16(dst, src) \
    asm volatile("cp.async.cg.shared.global [%0], [%1], 16;" :: "r"(dst), "l"(src))
#define CP_COMMIT() asm volatile("cp.async.commit_group;" ::: "memory")
#define CP_WAIT0()  asm volatile("cp.async.wait_group 0;" ::: "memory")
#define CP_WAIT1()  asm volatile("cp.async.wait_group 1;" ::: "memory")

// split f32 pair -> bf16x2 hi + bf16x2 lo (packed u32)
__device__ __forceinline__ void split2(float a, float b, uint32_t& hi, uint32_t& lo) {
    __nv_bfloat162 h, l;
    h.x = __float2bfloat16(a); h.y = __float2bfloat16(b);
    l.x = __float2bfloat16(a - __bfloat162float(h.x));
    l.y = __float2bfloat16(b - __bfloat162float(h.y));
    hi = *reinterpret_cast<uint32_t*>(&h);
    lo = *reinterpret_cast<uint32_t*>(&l);
}

// ===========================================================================
// Pre-split: fp32 -> bf16 hi/lo pair
// ===========================================================================
__global__ __launch_bounds__(256) void split_kernel(
    const float* __restrict__ in,
    __nv_bfloat16* __restrict__ hi, __nv_bfloat16* __restrict__ lo)
{
    int i = blockIdx.x * blockDim.x + threadIdx.x;
    float4 v = reinterpret_cast<const float4*>(in)[i];
    uint32_t h0, h1, l0, l1;
    split2(v.x, v.y, h0, l0);
    split2(v.z, v.w, h1, l1);
    reinterpret_cast<uint32_t*>(hi)[i * 2 + 0] = h0;
    reinterpret_cast<uint32_t*>(hi)[i * 2 + 1] = h1;
    reinterpret_cast<uint32_t*>(lo)[i * 2 + 0] = l0;
    reinterpret_cast<uint32_t*>(lo)[i * 2 + 1] = l1;
}

// ===========================================================================
// bf16 HMMA GEMM: C[m,n] = sum_k A[m,k]*W[n,k] with 3-term hi/lo split.
// mode 0: Cf fp32 [m][1024].
// mode 1: Chi/Clo bf16 split, head layout [b,h,s,dk], scaled by `scale`.
// ===========================================================================
#define ROWB   80
#define TILEB  (128 * ROWB)
#define STAGEB (4 * TILEB)
#define SMEMG  (2 * STAGEB)      // 81920 B

__global__ __launch_bounds__(256, 2) void gemm_bf16_kernel(
    const __nv_bfloat16* __restrict__ Ahi, const __nv_bfloat16* __restrict__ Alo,
    const __nv_bfloat16* __restrict__ Bhi, const __nv_bfloat16* __restrict__ Blo,
    float* __restrict__ Cf,
    __nv_bfloat16* __restrict__ Chi, __nv_bfloat16* __restrict__ Clo,
    int mode, float scale)
{
    extern __shared__ char smg[];
    const uint32_t sbase = smem_u32(smg);
    const int tid  = threadIdx.x;
    const int lane = tid & 31;
    const int wid  = tid >> 5;
    const int wm   = (wid & 3) * 32;
    const int wn   = (wid >> 2) * 64;
    const int m0   = blockIdx.y * 128;
    const int n0   = blockIdx.x * 128;

    const __nv_bfloat16* gsrc[4] = {
        Ahi + (size_t)m0 * 1024, Alo + (size_t)m0 * 1024,
        Bhi + (size_t)n0 * 1024, Blo + (size_t)n0 * 1024 };

    float acc[2][8][4];
#pragma unroll
    for (int i = 0; i < 2; i++)
#pragma unroll
        for (int j = 0; j < 8; j++)
#pragma unroll
            for (int r = 0; r < 4; r++) acc[i][j][r] = 0.f;

    auto issue = [&](int c, int s) {
#pragma unroll
        for (int l = 0; l < 8; l++) {
            int T  = l >> 1;
            int q  = tid + (l & 1) * 256;
            int row = q >> 2, cc = q & 3;
            uint32_t dst = sbase + s * STAGEB + T * TILEB + row * ROWB + cc * 16;
            const __nv_bfloat16* src = gsrc[T] + (size_t)row * 1024 + c * 32 + cc * 8;
            CP16(dst, src);
        }
        CP_COMMIT();
    };

    issue(0, 0);

    const int a_roff = (lane & 7) + ((lane >> 3) & 1) * 8;
    const int a_coff = ((lane >> 4) & 1) * 16;
    const int b_roff = (lane & 7) + ((lane >> 4) & 1) * 8;
    const int b_coff = ((lane >> 3) & 1) * 16;

    for (int c = 0; c < 32; c++) {
        const int s = c & 1;
        CP_WAIT0();
        __syncthreads();
        if (c < 31) issue(c + 1, s ^ 1);

        const uint32_t tA_hi = sbase + s * STAGEB;
        const uint32_t tA_lo = tA_hi + TILEB;
        const uint32_t tB_hi = tA_hi + 2 * TILEB;
        const uint32_t tB_lo = tA_hi + 3 * TILEB;

#pragma unroll
        for (int ks = 0; ks < 2; ks++) {
            uint32_t ah[2][4], al[2][4];
#pragma unroll
            for (int mt = 0; mt < 2; mt++) {
                uint32_t off = (uint32_t)(wm + mt * 16 + a_roff) * ROWB + ks * 32 + a_coff;
                ldsm4(ah[mt], tA_hi + off);
                ldsm4(al[mt], tA_lo + off);
            }
#pragma unroll
            for (int np = 0; np < 4; np++) {
                uint32_t bh[4], bl[4];
                uint32_t off = (uint32_t)(wn + np * 16 + b_roff) * ROWB + ks * 32 + b_coff;
                ldsm4(bh, tB_hi + off);
                ldsm4(bl, tB_lo + off);
#pragma unroll
                for (int mt = 0; mt < 2; mt++) {
#pragma unroll
                    for (int j = 0; j < 2; j++) {
                        float* d = acc[mt][np * 2 + j];
                        mma_bf16(d, ah[mt], bh + j * 2);
                        mma_bf16(d, ah[mt], bl + j * 2);
                        mma_bf16(d, al[mt], bh + j * 2);
                    }
                }
            }
        }
        __syncthreads();
    }

#pragma unroll
    for (int mt = 0; mt < 2; mt++) {
#pragma unroll
        for (int nt = 0; nt < 8; nt++) {
            int row0 = m0 + wm + mt * 16 + (lane >> 2);
            int col  = n0 + wn + nt * 8 + (lane & 3) * 2;
            float2 v0 = make_float2(acc[mt][nt][0], acc[mt][nt][1]);
            float2 v1 = make_float2(acc[mt][nt][2], acc[mt][nt][3]);
            if (mode == 1) {
                int h = col >> 6, dk = col & 63;
#pragma unroll
                for (int rr = 0; rr < 2; rr++) {
                    int row = row0 + rr * 8;
                    float2 v = rr ? v1 : v0;
                    size_t idx = (((size_t)((row >> 11) * H_ + h) * S_) + (row & 2047)) * DK_ + dk;
                    uint32_t hi, lo;
                    split2(v.x * scale, v.y * scale, hi, lo);
                    *reinterpret_cast<uint32_t*>(Chi + idx) = hi;
                    *reinterpret_cast<uint32_t*>(Clo + idx) = lo;
                }
            } else {
                *reinterpret_cast<float2*>(&Cf[(size_t)row0 * 1024 + col]) = v0;
                *reinterpret_cast<float2*>(&Cf[(size_t)(row0 + 8) * 1024 + col]) = v1;
            }
        }
    }
}

// ===========================================================================
// Flash attention on HMMA, 3-term bf16 split.
// CTA: 128 q-rows x full key loop (64-key blocks). 8 warps, 16 q-rows each.
// Q/K: [row][dk] bf16 hi/lo (Q pre-scaled by 1/8). V natural [key][dk] via
// ldmatrix.trans. Output written as bf16 hi/lo split into Ahi/Alo [m][1024].
// ===========================================================================
#define AROW 144
#define QOFF 0              // 2 * 128*144 = 36864
#define KOFF 36864          // 2 bufs * 2 (hi/lo) * 64*144 = 36864
#define VOFF 73728
#define MOFF 110592         // 2 * 256
#define ASMEM 111104

__global__ __launch_bounds__(256, 2) void attn_mma_kernel(
    const __nv_bfloat16* __restrict__ Qhi, const __nv_bfloat16* __restrict__ Qlo,
    const __nv_bfloat16* __restrict__ Khi, const __nv_bfloat16* __restrict__ Klo,
    const __nv_bfloat16* __restrict__ Vhi, const __nv_bfloat16* __restrict__ Vlo,
    const int* __restrict__ mask,
    __nv_bfloat16* __restrict__ Ohi, __nv_bfloat16* __restrict__ Olo)
{
    extern __shared__ char sma[];
    const uint32_t sbase = smem_u32(sma);
    const int tid  = threadIdx.x;
    const int lane = tid & 31;
    const int wid  = tid >> 5;
    const int wq   = wid * 16;          // warp's q-row offset in CTA tile
    const int q0   = blockIdx.x * 128;
    const int h    = blockIdx.y;
    const int b    = blockIdx.z;

    const size_t bh = ((size_t)b * H_ + h) * S_ * DK_;
    const __nv_bfloat16* Qhi_b = Qhi + bh;
    const __nv_bfloat16* Qlo_b = Qlo + bh;
    const __nv_bfloat16* Khi_b = Khi + bh;
    const __nv_bfloat16* Klo_b = Klo + bh;
    const __nv_bfloat16* Vhi_b = Vhi + bh;
    const __nv_bfloat16* Vlo_b = Vlo + bh;
    const int* mrow = mask + b * S_;

    // ---- prologue: Q tile (once) + K/V/mask block 0 ----
#pragma unroll
    for (int i = 0; i < 8; i++) {
        int c = tid + i * 256;             // 0..2047
        int T = c >> 10;
        int idx = c & 1023;
        int row = idx >> 3, ch = idx & 7;
        uint32_t dst = sbase + QOFF + T * 18432 + row * AROW + ch * 16;
        const __nv_bfloat16* src = (T ? Qlo_b : Qhi_b) + (size_t)(q0 + row) * 64 + ch * 8;
        CP16(dst, src);
    }
    auto issueKV = [&](int kb, int s) {
#pragma unroll
        for (int i = 0; i < 4; i++) {
            int c = tid + i * 256;         // 0..1023
            int T = c >> 9;
            int idx = c & 511;
            int row = idx >> 3, ch = idx & 7;
            uint32_t doff = s * 9216 + T * 18432 + (uint32_t)row * AROW + ch * 16;
            size_t soff = (size_t)(kb * 64 + row) * 64 + ch * 8;
            CP16(sbase + KOFF + doff, (T ? Klo_b : Khi_b) + soff);
            CP16(sbase + VOFF + doff, (T ? Vlo_b : Vhi_b) + soff);
        }
        if (tid < 16)
            CP16(sbase + MOFF + s * 256 + tid * 16, mrow + kb * 64 + tid * 4);
    };
    issueKV(0, 0);
    CP_COMMIT();

    // fragment addressing
    const int a_roff  = (lane & 7) + ((lane >> 3) & 1) * 8;
    const int a_coff  = ((lane >> 4) & 1) * 16;
    const int b_roff  = (lane & 7) + ((lane >> 4) & 1) * 8;
    const int b_coff  = ((lane >> 3) & 1) * 16;
    const int vb_roff = (lane & 7) + ((lane >> 3) & 1) * 8;   // key within chunk
    const int vb_coff = ((lane >> 4) & 1) * 16;               // dk bytes

    float O[8][4];
#pragma unroll
    for (int i = 0; i < 8; i++)
#pragma unroll
        for (int j = 0; j < 4; j++) O[i][j] = 0.f;
    float mM[2] = {-1e30f, -1e30f};
    float lL[2] = {0.f, 0.f};

    for (int kb = 0; kb < 32; kb++) {
        const int s = kb & 1;
        if (kb < 31) { issueKV(kb + 1, s ^ 1); CP_COMMIT(); CP_WAIT1(); }
        else         { CP_WAIT0(); }
        __syncthreads();

        // ---- scores = Q @ K^T (pre-scaled) ----
        float sc[8][4];
#pragma unroll
        for (int i = 0; i < 8; i++)
#pragma unroll
            for (int j = 0; j < 4; j++) sc[i][j] = 0.f;

        const uint32_t kb_hi = sbase + KOFF + s * 9216;
        const uint32_t kb_lo = kb_hi + 18432;
#pragma unroll
        for (int ks = 0; ks < 4; ks++) {
            uint32_t ah[4], al[4];
            uint32_t aoff = (uint32_t)(wq + a_roff) * AROW + ks * 32 + a_coff;
            ldsm4(ah, sbase + QOFF + aoff);
            ldsm4(al, sbase + QOFF + 18432 + aoff);
#pragma unroll
            for (int np = 0; np < 4; np++) {
                uint32_t bh2[4], bl2[4];
                uint32_t boff = (uint32_t)(np * 16 + b_roff) * AROW + ks * 32 + b_coff;
                ldsm4(bh2, kb_hi + boff);
                ldsm4(bl2, kb_lo + boff);
#pragma unroll
                for (int j = 0; j < 2; j++) {
                    float* d = sc[np * 2 + j];
                    mma_bf16(d, ah, bh2 + j * 2);
                    mma_bf16(d, ah, bl2 + j * 2);
                    mma_bf16(d, al, bh2 + j * 2);
                }
            }
        }

        // ---- mask ----
        const int c0 = (lane & 3) * 2;
#pragma unroll
        for (int st = 0; st < 8; st++) {
            int2 mv = *reinterpret_cast<const int2*>(
                sma + (MOFF + s * 256) + (st * 8 + c0) * 4);
            if (mv.x == 0) { sc[st][0] = -1e9f; sc[st][2] = -1e9f; }
            if (mv.y == 0) { sc[st][1] = -1e9f; sc[st][3] = -1e9f; }
        }

        // ---- online softmax (2 rows per thread: r, r+8) ----
        float alpha[2];
#pragma unroll
        for (int rh = 0; rh < 2; rh++) {
            float mx = -1e30f;
#pragma unroll
            for (int st = 0; st < 8; st++)
                mx = fmaxf(mx, fmaxf(sc[st][rh * 2], sc[st][rh * 2 + 1]));
            mx = fmaxf(mx, __shfl_xor_sync(0xffffffffu, mx, 1));
            mx = fmaxf(mx, __shfl_xor_sync(0xffffffffu, mx, 2));
            float mn = fmaxf(mM[rh], mx);
            alpha[rh] = __expf(mM[rh] - mn);
            mM[rh] = mn;
            float rsum = 0.f;
#pragma unroll
            for (int st = 0; st < 8; st++) {
                float p0 = __expf(sc[st][rh * 2] - mn);
                float p1 = __expf(sc[st][rh * 2 + 1] - mn);
                sc[st][rh * 2] = p0; sc[st][rh * 2 + 1] = p1;
                rsum += p0 + p1;
            }
            rsum += __shfl_xor_sync(0xffffffffu, rsum, 1);
            rsum += __shfl_xor_sync(0xffffffffu, rsum, 2);
            lL[rh] = lL[rh] * alpha[rh] + rsum;
        }
#pragma unroll
        for (int nt = 0; nt < 8; nt++) {
            O[nt][0] *= alpha[0]; O[nt][1] *= alpha[0];
            O[nt][2] *= alpha[1]; O[nt][3] *= alpha[1];
        }

        // ---- O += P @ V (P from registers, V via ldmatrix.trans) ----
        const uint32_t vb_hi = sbase + VOFF + s * 9216;
        const uint32_t vb_lo = vb_hi + 18432;
#pragma unroll
        for (int ks = 0; ks < 4; ks++) {   // 16-key chunks
            uint32_t ph[4], pl[4];
            split2(sc[2 * ks][0],     sc[2 * ks][1],     ph[0], pl[0]);
            split2(sc[2 * ks][2],     sc[2 * ks][3],     ph[1], pl[1]);
            split2(sc[2 * ks + 1][0], sc[2 * ks + 1][1], ph[2], pl[2]);
            split2(sc[2 * ks + 1][2], sc[2 * ks + 1][3], ph[3], pl[3]);
#pragma unroll
            for (int np = 0; np < 4; np++) {  // 16-dk chunks
                uint32_t vh[4], vl[4];
                uint32_t voff = (uint32_t)(ks * 16 + vb_roff) * AROW + np * 32 + vb_coff;
                ldsm4t(vh, vb_hi + voff);
                ldsm4t(vl, vb_lo + voff);
#pragma unroll
                for (int j = 0; j < 2; j++) {
                    float* d = O[np * 2 + j];
                    mma_bf16(d, ph, vh + j * 2);
                    mma_bf16(d, ph, vl + j * 2);
                    mma_bf16(d, pl, vh + j * 2);
                }
            }
        }
        __syncthreads();
    }

    // ---- epilogue: O /= l, write bf16 hi/lo into [m][1024] ----
#pragma unroll
    for (int rh = 0; rh < 2; rh++) {
        float inv = 1.f / lL[rh];
        int row = q0 + wq + (lane >> 2) + rh * 8;
        size_t mrow_o = ((size_t)b * S_ + row) * DM_ + h * 64;
#pragma unroll
        for (int nt = 0; nt < 8; nt++) {
            int col = nt * 8 + (lane & 3) * 2;
            uint32_t hi, lo;
            split2(O[nt][rh * 2] * inv, O[nt][rh * 2 + 1] * inv, hi, lo);
            *reinterpret_cast<uint32_t*>(Ohi + mrow_o + col) = hi;
            *reinterpret_cast<uint32_t*>(Olo + mrow_o + col) = lo;
        }
    }
}

// ---------------------------------------------------------------------------
extern "C" void kernel_launch(void* const* d_in, const int* in_sizes, int n_in,
                              void* d_out, int out_size)
{
    const float* q    = (const float*)d_in[0];
    const float* k    = (const float*)d_in[1];
    const float* v    = (const float*)d_in[2];
    const int*   mask = (const int*)d_in[3];
    const float* Wq   = (const float*)d_in[4];
    const float* Wk   = (const float*)d_in[5];
    const float* Wv   = (const float*)d_in[6];
    const float* Wo   = (const float*)d_in[7];
    float* out = (float*)d_out;

    __nv_bfloat16 *ahi, *alo, *whi, *wlo, *qhi, *qlo, *khi, *klo, *vhi, *vlo;
    cudaGetSymbolAddress((void**)&ahi, g_Ahi);
    cudaGetSymbolAddress((void**)&alo, g_Alo);
    cudaGetSymbolAddress((void**)&whi, g_Whi);
    cudaGetSymbolAddress((void**)&wlo, g_Wlo);
    cudaGetSymbolAddress((void**)&qhi, g_Qhi);
    cudaGetSymbolAddress((void**)&qlo, g_Qlo);
    cudaGetSymbolAddress((void**)&khi, g_Khi);
    cudaGetSymbolAddress((void**)&klo, g_Klo);
    cudaGetSymbolAddress((void**)&vhi, g_Vhi);
    cudaGetSymbolAddress((void**)&vlo, g_Vlo);

    cudaFuncSetAttribute(gemm_bf16_kernel,
                         cudaFuncAttributeMaxDynamicSharedMemorySize, SMEMG);
    cudaFuncSetAttribute(attn_mma_kernel,
                         cudaFuncAttributeMaxDynamicSharedMemorySize, ASMEM);

    const int nA4 = M_ * DM_ / 4;
    const int nW4 = DM_ * DM_ / 4;
    dim3 gg(DM_ / 128, M_ / 128);

    // Q projection (pre-scale by 1/sqrt(dk) = 0.125)
    split_kernel<<<nA4 / 256, 256>>>(q, ahi, alo);
    split_kernel<<<nW4 / 256, 256>>>(Wq, whi, wlo);
    gemm_bf16_kernel<<<gg, 256, SMEMG>>>(ahi, alo, whi, wlo, nullptr, qhi, qlo, 1, 0.125f);
    // K projection
    split_kernel<<<nA4 / 256, 256>>>(k, ahi, alo);
    split_kernel<<<nW4 / 256, 256>>>(Wk, whi, wlo);
    gemm_bf16_kernel<<<gg, 256, SMEMG>>>(ahi, alo, whi, wlo, nullptr, khi, klo, 1, 1.0f);
    // V projection
    split_kernel<<<nA4 / 256, 256>>>(v, ahi, alo);
    split_kernel<<<nW4 / 256, 256>>>(Wv, whi, wlo);
    gemm_bf16_kernel<<<gg, 256, SMEMG>>>(ahi, alo, whi, wlo, nullptr, vhi, vlo, 1, 1.0f);

    // attention (writes bf16 hi/lo merged-head output into ahi/alo)
    attn_mma_kernel<<<dim3(S_ / 128, H_, B_), 256, ASMEM>>>(
        qhi, qlo, khi, klo, vhi, vlo, mask, ahi, alo);

    // output projection (fp32 result)
    split_kernel<<<nW4 / 256, 256>>>(Wo, whi, wlo);
    gemm_bf16_kernel<<<gg, 256, SMEMG>>>(ahi, alo, whi, wlo, out, nullptr, nullptr, 0, 1.0f);
}

// round 12
// speedup vs baseline: 1.0015x; 1.0015x over previous
#include <cuda_runtime.h>
#include <cuda_bf16.h>
#include <cstdint>

#define B_ 4
#define S_ 2048
#define DM_ 1024
#define H_ 16
#define DK_ 64
#define M_ (B_ * S_)   // 8192

// Scratch (device globals; allocation-free per harness rules)
__device__ __nv_bfloat16 g_Ahi[M_ * DM_];
__device__ __nv_bfloat16 g_Alo[M_ * DM_];
__device__ __nv_bfloat16 g_Whi[DM_ * DM_];
__device__ __nv_bfloat16 g_Wlo[DM_ * DM_];
__device__ __nv_bfloat16 g_Qhi[B_ * H_ * S_ * DK_];
__device__ __nv_bfloat16 g_Qlo[B_ * H_ * S_ * DK_];
__device__ __nv_bfloat16 g_Khi[B_ * H_ * S_ * DK_];
__device__ __nv_bfloat16 g_Klo[B_ * H_ * S_ * DK_];
__device__ __nv_bfloat16 g_Vhi[B_ * H_ * S_ * DK_];
__device__ __nv_bfloat16 g_Vlo[B_ * H_ * S_ * DK_];

// ===========================================================================
// Base-ISA helpers (valid on sm_103 WITHOUT the 'a' feature set)
// ===========================================================================
__device__ __forceinline__ uint32_t smem_u32(const void* p) {
    uint32_t a;
    asm("{ .reg .u64 t; cvta.to.shared.u64 t, %1; cvt.u32.u64 %0, t; }"
        : "=r"(a) : "l"(p));
    return a;
}
__device__ __forceinline__ void ldsm4(uint32_t* r, uint32_t addr) {
    asm volatile("ldmatrix.sync.aligned.m8n8.x4.shared.b16 {%0,%1,%2,%3}, [%4];"
                 : "=r"(r[0]), "=r"(r[1]), "=r"(r[2]), "=r"(r[3]) : "r"(addr));
}
__device__ __forceinline__ void ldsm4t(uint32_t* r, uint32_t addr) {
    asm volatile("ldmatrix.sync.aligned.m8n8.x4.trans.shared.b16 {%0,%1,%2,%3}, [%4];"
                 : "=r"(r[0]), "=r"(r[1]), "=r"(r[2]), "=r"(r[3]) : "r"(addr));
}
__device__ __forceinline__ void mma_bf16(float* d, const uint32_t* a, const uint32_t* b) {
    asm volatile(
        "mma.sync.aligned.m16n8k16.row.col.f32.bf16.bf16.f32 "
        "{%0,%1,%2,%3}, {%4,%5,%6,%7}, {%8,%9}, {%0,%1,%2,%3};"
        : "+f"(d[0]), "+f"(d[1]), "+f"(d[2]), "+f"(d[3])
        : "r"(a[0]), "r"(a[1]), "r"(a[2]), "r"(a[3]), "r"(b[0]), "r"(b[1]));
}
#define CP16(dst, src) \
    asm volatile("cp.async.cg.shared.global [%0], [%1], 16;" :: "r"(dst), "l"(src))
#define CP_COMMIT() asm volatile("cp.async.commit_group;" ::: "memory")
#define CP_WAIT0()  asm volatile("cp.async.wait_group 0;" ::: "memory")
#define CP_WAIT1()  asm volatile("cp.async.wait_group 1;" ::: "memory")

// split f32 pair -> bf16x2 hi + bf16x2 lo (packed u32)
__device__ __forceinline__ void split2(float a, float b, uint32_t& hi, uint32_t& lo) {
    __nv_bfloat162 h, l;
    h.x = __float2bfloat16(a); h.y = __float2bfloat16(b);
    l.x = __float2bfloat16(a - __bfloat162float(h.x));
    l.y = __float2bfloat16(b - __bfloat162float(h.y));
    hi = *reinterpret_cast<uint32_t*>(&h);
    lo = *reinterpret_cast<uint32_t*>(&l);
}

// ===========================================================================
// Pre-split: fp32 -> bf16 hi/lo pair
// ===========================================================================
__global__ __launch_bounds__(256) void split_kernel(
    const float* __restrict__ in,
    __nv_bfloat16* __restrict__ hi, __nv_bfloat16* __restrict__ lo)
{
    int i = blockIdx.x * blockDim.x + threadIdx.x;
    float4 v = reinterpret_cast<const float4*>(in)[i];
    uint32_t h0, h1, l0, l1;
    split2(v.x, v.y, h0, l0);
    split2(v.z, v.w, h1, l1);
    reinterpret_cast<uint32_t*>(hi)[i * 2 + 0] = h0;
    reinterpret_cast<uint32_t*>(hi)[i * 2 + 1] = h1;
    reinterpret_cast<uint32_t*>(lo)[i * 2 + 0] = l0;
    reinterpret_cast<uint32_t*>(lo)[i * 2 + 1] = l1;
}

// ===========================================================================
// bf16 HMMA GEMM: C[m,n] = sum_k A[m,k]*W[n,k] with 3-term hi/lo split.
// mode 0: Cf fp32 [m][1024].
// mode 1: Chi/Clo bf16 split, head layout [b,h,s,dk], scaled by `scale`.
// ===========================================================================
#define ROWB   80
#define TILEB  (128 * ROWB)
#define STAGEB (4 * TILEB)
#define SMEMG  (2 * STAGEB)      // 81920 B

__global__ __launch_bounds__(256, 2) void gemm_bf16_kernel(
    const __nv_bfloat16* __restrict__ Ahi, const __nv_bfloat16* __restrict__ Alo,
    const __nv_bfloat16* __restrict__ Bhi, const __nv_bfloat16* __restrict__ Blo,
    float* __restrict__ Cf,
    __nv_bfloat16* __restrict__ Chi, __nv_bfloat16* __restrict__ Clo,
    int mode, float scale)
{
    extern __shared__ char smg[];
    const uint32_t sbase = smem_u32(smg);
    const int tid  = threadIdx.x;
    const int lane = tid & 31;
    const int wid  = tid >> 5;
    const int wm   = (wid & 3) * 32;
    const int wn   = (wid >> 2) * 64;
    const int m0   = blockIdx.y * 128;
    const int n0   = blockIdx.x * 128;

    const __nv_bfloat16* gsrc[4] = {
        Ahi + (size_t)m0 * 1024, Alo + (size_t)m0 * 1024,
        Bhi + (size_t)n0 * 1024, Blo + (size_t)n0 * 1024 };

    float acc[2][8][4];
#pragma unroll
    for (int i = 0; i < 2; i++)
#pragma unroll
        for (int j = 0; j < 8; j++)
#pragma unroll
            for (int r = 0; r < 4; r++) acc[i][j][r] = 0.f;

    auto issue = [&](int c, int s) {
#pragma unroll
        for (int l = 0; l < 8; l++) {
            int T  = l >> 1;
            int q  = tid + (l & 1) * 256;
            int row = q >> 2, cc = q & 3;
            uint32_t dst = sbase + s * STAGEB + T * TILEB + row * ROWB + cc * 16;
            const __nv_bfloat16* src = gsrc[T] + (size_t)row * 1024 + c * 32 + cc * 8;
            CP16(dst, src);
        }
        CP_COMMIT();
    };

    issue(0, 0);

    const int a_roff = (lane & 7) + ((lane >> 3) & 1) * 8;
    const int a_coff = ((lane >> 4) & 1) * 16;
    const int b_roff = (lane & 7) + ((lane >> 4) & 1) * 8;
    const int b_coff = ((lane >> 3) & 1) * 16;

    for (int c = 0; c < 32; c++) {
        const int s = c & 1;
        CP_WAIT0();
        __syncthreads();
        if (c < 31) issue(c + 1, s ^ 1);

        const uint32_t tA_hi = sbase + s * STAGEB;
        const uint32_t tA_lo = tA_hi + TILEB;
        const uint32_t tB_hi = tA_hi + 2 * TILEB;
        const uint32_t tB_lo = tA_hi + 3 * TILEB;

#pragma unroll
        for (int ks = 0; ks < 2; ks++) {
            uint32_t ah[2][4], al[2][4];
#pragma unroll
            for (int mt = 0; mt < 2; mt++) {
                uint32_t off = (uint32_t)(wm + mt * 16 + a_roff) * ROWB + ks * 32 + a_coff;
                ldsm4(ah[mt], tA_hi + off);
                ldsm4(al[mt], tA_lo + off);
            }
#pragma unroll
            for (int np = 0; np < 4; np++) {
                uint32_t bh[4], bl[4];
                uint32_t off = (uint32_t)(wn + np * 16 + b_roff) * ROWB + ks * 32 + b_coff;
                ldsm4(bh, tB_hi + off);
                ldsm4(bl, tB_lo + off);
#pragma unroll
                for (int mt = 0; mt < 2; mt++) {
#pragma unroll
                    for (int j = 0; j < 2; j++) {
                        float* d = acc[mt][np * 2 + j];
                        mma_bf16(d, ah[mt], bh + j * 2);
                        mma_bf16(d, ah[mt], bl + j * 2);
                        mma_bf16(d, al[mt], bh + j * 2);
                    }
                }
            }
        }
        __syncthreads();
    }

#pragma unroll
    for (int mt = 0; mt < 2; mt++) {
#pragma unroll
        for (int nt = 0; nt < 8; nt++) {
            int row0 = m0 + wm + mt * 16 + (lane >> 2);
            int col  = n0 + wn + nt * 8 + (lane & 3) * 2;
            float2 v0 = make_float2(acc[mt][nt][0], acc[mt][nt][1]);
            float2 v1 = make_float2(acc[mt][nt][2], acc[mt][nt][3]);
            if (mode == 1) {
                int h = col >> 6, dk = col & 63;
#pragma unroll
                for (int rr = 0; rr < 2; rr++) {
                    int row = row0 + rr * 8;
                    float2 v = rr ? v1 : v0;
                    size_t idx = (((size_t)((row >> 11) * H_ + h) * S_) + (row & 2047)) * DK_ + dk;
                    uint32_t hi, lo;
                    split2(v.x * scale, v.y * scale, hi, lo);
                    *reinterpret_cast<uint32_t*>(Chi + idx) = hi;
                    *reinterpret_cast<uint32_t*>(Clo + idx) = lo;
                }
            } else {
                *reinterpret_cast<float2*>(&Cf[(size_t)row0 * 1024 + col]) = v0;
                *reinterpret_cast<float2*>(&Cf[(size_t)(row0 + 8) * 1024 + col]) = v1;
            }
        }
    }
}

// ===========================================================================
// Flash attention on HMMA, 3-term bf16 split.
// CTA: 128 q-rows x full key loop (64-key blocks). 8 warps, 16 q-rows each.
// Q/K: [row][dk] bf16 hi/lo (Q pre-scaled by 1/8). V natural [key][dk] via
// ldmatrix.trans. Output written as bf16 hi/lo split into Ahi/Alo [m][1024].
// ===========================================================================
#define AROW 144
#define QOFF 0              // 2 * 128*144 = 36864
#define KOFF 36864          // 2 bufs * 2 (hi/lo) * 64*144 = 36864
#define VOFF 73728
#define MOFF 110592         // 2 * 256
#define ASMEM 111104

__global__ __launch_bounds__(256, 2) void attn_mma_kernel(
    const __nv_bfloat16* __restrict__ Qhi, const __nv_bfloat16* __restrict__ Qlo,
    const __nv_bfloat16* __restrict__ Khi, const __nv_bfloat16* __restrict__ Klo,
    const __nv_bfloat16* __restrict__ Vhi, const __nv_bfloat16* __restrict__ Vlo,
    const int* __restrict__ mask,
    __nv_bfloat16* __restrict__ Ohi, __nv_bfloat16* __restrict__ Olo)
{
    extern __shared__ char sma[];
    const uint32_t sbase = smem_u32(sma);
    const int tid  = threadIdx.x;
    const int lane = tid & 31;
    const int wid  = tid >> 5;
    const int wq   = wid * 16;          // warp's q-row offset in CTA tile
    const int q0   = blockIdx.x * 128;
    const int h    = blockIdx.y;
    const int b    = blockIdx.z;

    const size_t bh = ((size_t)b * H_ + h) * S_ * DK_;
    const __nv_bfloat16* Qhi_b = Qhi + bh;
    const __nv_bfloat16* Qlo_b = Qlo + bh;
    const __nv_bfloat16* Khi_b = Khi + bh;
    const __nv_bfloat16* Klo_b = Klo + bh;
    const __nv_bfloat16* Vhi_b = Vhi + bh;
    const __nv_bfloat16* Vlo_b = Vlo + bh;
    const int* mrow = mask + b * S_;

    // ---- prologue: Q tile (once) + K/V/mask block 0 ----
#pragma unroll
    for (int i = 0; i < 8; i++) {
        int c = tid + i * 256;             // 0..2047
        int T = c >> 10;
        int idx = c & 1023;
        int row = idx >> 3, ch = idx & 7;
        uint32_t dst = sbase + QOFF + T * 18432 + row * AROW + ch * 16;
        const __nv_bfloat16* src = (T ? Qlo_b : Qhi_b) + (size_t)(q0 + row) * 64 + ch * 8;
        CP16(dst, src);
    }
    auto issueKV = [&](int kb, int s) {
#pragma unroll
        for (int i = 0; i < 4; i++) {
            int c = tid + i * 256;         // 0..1023
            int T = c >> 9;
            int idx = c & 511;
            int row = idx >> 3, ch = idx & 7;
            uint32_t doff = s * 9216 + T * 18432 + (uint32_t)row * AROW + ch * 16;
            size_t soff = (size_t)(kb * 64 + row) * 64 + ch * 8;
            CP16(sbase + KOFF + doff, (T ? Klo_b : Khi_b) + soff);
            CP16(sbase + VOFF + doff, (T ? Vlo_b : Vhi_b) + soff);
        }
        if (tid < 16)
            CP16(sbase + MOFF + s * 256 + tid * 16, mrow + kb * 64 + tid * 4);
    };
    issueKV(0, 0);
    CP_COMMIT();

    // fragment addressing
    const int a_roff  = (lane & 7) + ((lane >> 3) & 1) * 8;
    const int a_coff  = ((lane >> 4) & 1) * 16;
    const int b_roff  = (lane & 7) + ((lane >> 4) & 1) * 8;
    const int b_coff  = ((lane >> 3) & 1) * 16;
    const int vb_roff = (lane & 7) + ((lane >> 3) & 1) * 8;   // key within chunk
    const int vb_coff = ((lane >> 4) & 1) * 16;               // dk bytes

    float O[8][4];
#pragma unroll
    for (int i = 0; i < 8; i++)
#pragma unroll
        for (int j = 0; j < 4; j++) O[i][j] = 0.f;
    float mM[2] = {-1e30f, -1e30f};
    float lL[2] = {0.f, 0.f};

    for (int kb = 0; kb < 32; kb++) {
        const int s = kb & 1;
        if (kb < 31) { issueKV(kb + 1, s ^ 1); CP_COMMIT(); CP_WAIT1(); }
        else         { CP_WAIT0(); }
        __syncthreads();

        // ---- scores = Q @ K^T (pre-scaled) ----
        float sc[8][4];
#pragma unroll
        for (int i = 0; i < 8; i++)
#pragma unroll
            for (int j = 0; j < 4; j++) sc[i][j] = 0.f;

        const uint32_t kb_hi = sbase + KOFF + s * 9216;
        const uint32_t kb_lo = kb_hi + 18432;
#pragma unroll
        for (int ks = 0; ks < 4; ks++) {
            uint32_t ah[4], al[4];
            uint32_t aoff = (uint32_t)(wq + a_roff) * AROW + ks * 32 + a_coff;
            ldsm4(ah, sbase + QOFF + aoff);
            ldsm4(al, sbase + QOFF + 18432 + aoff);
#pragma unroll
            for (int np = 0; np < 4; np++) {
                uint32_t bh2[4], bl2[4];
                uint32_t boff = (uint32_t)(np * 16 + b_roff) * AROW + ks * 32 + b_coff;
                ldsm4(bh2, kb_hi + boff);
                ldsm4(bl2, kb_lo + boff);
#pragma unroll
                for (int j = 0; j < 2; j++) {
                    float* d = sc[np * 2 + j];
                    mma_bf16(d, ah, bh2 + j * 2);
                    mma_bf16(d, ah, bl2 + j * 2);
                    mma_bf16(d, al, bh2 + j * 2);
                }
            }
        }

        // ---- mask ----
        const int c0 = (lane & 3) * 2;
#pragma unroll
        for (int st = 0; st < 8; st++) {
            int2 mv = *reinterpret_cast<const int2*>(
                sma + (MOFF + s * 256) + (st * 8 + c0) * 4);
            if (mv.x == 0) { sc[st][0] = -1e9f; sc[st][2] = -1e9f; }
            if (mv.y == 0) { sc[st][1] = -1e9f; sc[st][3] = -1e9f; }
        }

        // ---- online softmax (2 rows per thread: r, r+8) ----
        float alpha[2];
#pragma unroll
        for (int rh = 0; rh < 2; rh++) {
            float mx = -1e30f;
#pragma unroll
            for (int st = 0; st < 8; st++)
                mx = fmaxf(mx, fmaxf(sc[st][rh * 2], sc[st][rh * 2 + 1]));
            mx = fmaxf(mx, __shfl_xor_sync(0xffffffffu, mx, 1));
            mx = fmaxf(mx, __shfl_xor_sync(0xffffffffu, mx, 2));
            float mn = fmaxf(mM[rh], mx);
            alpha[rh] = __expf(mM[rh] - mn);
            mM[rh] = mn;
            float rsum = 0.f;
#pragma unroll
            for (int st = 0; st < 8; st++) {
                float p0 = __expf(sc[st][rh * 2] - mn);
                float p1 = __expf(sc[st][rh * 2 + 1] - mn);
                sc[st][rh * 2] = p0; sc[st][rh * 2 + 1] = p1;
                rsum += p0 + p1;
            }
            rsum += __shfl_xor_sync(0xffffffffu, rsum, 1);
            rsum += __shfl_xor_sync(0xffffffffu, rsum, 2);
            lL[rh] = lL[rh] * alpha[rh] + rsum;
        }
#pragma unroll
        for (int nt = 0; nt < 8; nt++) {
            O[nt][0] *= alpha[0]; O[nt][1] *= alpha[0];
            O[nt][2] *= alpha[1]; O[nt][3] *= alpha[1];
        }

        // ---- O += P @ V (P from registers, V via ldmatrix.trans) ----
        const uint32_t vb_hi = sbase + VOFF + s * 9216;
        const uint32_t vb_lo = vb_hi + 18432;
#pragma unroll
        for (int ks = 0; ks < 4; ks++) {   // 16-key chunks
            uint32_t ph[4], pl[4];
            split2(sc[2 * ks][0],     sc[2 * ks][1],     ph[0], pl[0]);
            split2(sc[2 * ks][2],     sc[2 * ks][3],     ph[1], pl[1]);
            split2(sc[2 * ks + 1][0], sc[2 * ks + 1][1], ph[2], pl[2]);
            split2(sc[2 * ks + 1][2], sc[2 * ks + 1][3], ph[3], pl[3]);
#pragma unroll
            for (int np = 0; np < 4; np++) {  // 16-dk chunks
                uint32_t vh[4], vl[4];
                uint32_t voff = (uint32_t)(ks * 16 + vb_roff) * AROW + np * 32 + vb_coff;
                ldsm4t(vh, vb_hi + voff);
                ldsm4t(vl, vb_lo + voff);
#pragma unroll
                for (int j = 0; j < 2; j++) {
                    float* d = O[np * 2 + j];
                    mma_bf16(d, ph, vh + j * 2);
                    mma_bf16(d, ph, vl + j * 2);
                    mma_bf16(d, pl, vh + j * 2);
                }
            }
        }
        __syncthreads();
    }

    // ---- epilogue: O /= l, write bf16 hi/lo into [m][1024] ----
#pragma unroll
    for (int rh = 0; rh < 2; rh++) {
        float inv = 1.f / lL[rh];
        int row = q0 + wq + (lane >> 2) + rh * 8;
        size_t mrow_o = ((size_t)b * S_ + row) * DM_ + h * 64;
#pragma unroll
        for (int nt = 0; nt < 8; nt++) {
            int col = nt * 8 + (lane & 3) * 2;
            uint32_t hi, lo;
            split2(O[nt][rh * 2] * inv, O[nt][rh * 2 + 1] * inv, hi, lo);
            *reinterpret_cast<uint32_t*>(Ohi + mrow_o + col) = hi;
            *reinterpret_cast<uint32_t*>(Olo + mrow_o + col) = lo;
        }
    }
}

// ---------------------------------------------------------------------------
extern "C" void kernel_launch(void* const* d_in, const int* in_sizes, int n_in,
                              void* d_out, int out_size)
{
    const float* q    = (const float*)d_in[0];
    const float* k    = (const float*)d_in[1];
    const float* v    = (const float*)d_in[2];
    const int*   mask = (const int*)d_in[3];
    const float* Wq   = (const float*)d_in[4];
    const float* Wk   = (const float*)d_in[5];
    const float* Wv   = (const float*)d_in[6];
    const float* Wo   = (const float*)d_in[7];
    float* out = (float*)d_out;

    __nv_bfloat16 *ahi, *alo, *whi, *wlo, *qhi, *qlo, *khi, *klo, *vhi, *vlo;
    cudaGetSymbolAddress((void**)&ahi, g_Ahi);
    cudaGetSymbolAddress((void**)&alo, g_Alo);
    cudaGetSymbolAddress((void**)&whi, g_Whi);
    cudaGetSymbolAddress((void**)&wlo, g_Wlo);
    cudaGetSymbolAddress((void**)&qhi, g_Qhi);
    cudaGetSymbolAddress((void**)&qlo, g_Qlo);
    cudaGetSymbolAddress((void**)&khi, g_Khi);
    cudaGetSymbolAddress((void**)&klo, g_Klo);
    cudaGetSymbolAddress((void**)&vhi, g_Vhi);
    cudaGetSymbolAddress((void**)&vlo, g_Vlo);

    cudaFuncSetAttribute(gemm_bf16_kernel,
                         cudaFuncAttributeMaxDynamicSharedMemorySize, SMEMG);
    cudaFuncSetAttribute(attn_mma_kernel,
                         cudaFuncAttributeMaxDynamicSharedMemorySize, ASMEM);

    const int nA4 = M_ * DM_ / 4;
    const int nW4 = DM_ * DM_ / 4;
    dim3 gg(DM_ / 128, M_ / 128);

    // Q projection (pre-scale by 1/sqrt(dk) = 0.125)
    split_kernel<<<nA4 / 256, 256>>>(q, ahi, alo);
    split_kernel<<<nW4 / 256, 256>>>(Wq, whi, wlo);
    gemm_bf16_kernel<<<gg, 256, SMEMG>>>(ahi, alo, whi, wlo, nullptr, qhi, qlo, 1, 0.125f);
    // K projection
    split_kernel<<<nA4 / 256, 256>>>(k, ahi, alo);
    split_kernel<<<nW4 / 256, 256>>>(Wk, whi, wlo);
    gemm_bf16_kernel<<<gg, 256, SMEMG>>>(ahi, alo, whi, wlo, nullptr, khi, klo, 1, 1.0f);
    // V projection
    split_kernel<<<nA4 / 256, 256>>>(v, ahi, alo);
    split_kernel<<<nW4 / 256, 256>>>(Wv, whi, wlo);
    gemm_bf16_kernel<<<gg, 256, SMEMG>>>(ahi, alo, whi, wlo, nullptr, vhi, vlo, 1, 1.0f);

    // attention (writes bf16 hi/lo merged-head output into ahi/alo)
    attn_mma_kernel<<<dim3(S_ / 128, H_, B_), 256, ASMEM>>>(
        qhi, qlo, khi, klo, vhi, vlo, mask, ahi, alo);

    // output projection (fp32 result)
    split_kernel<<<nW4 / 256, 256>>>(Wo, whi, wlo);
    gemm_bf16_kernel<<<gg, 256, SMEMG>>>(ahi, alo, whi, wlo, out, nullptr, nullptr, 0, 1.0f);
}

// round 13
// speedup vs baseline: 1.0048x; 1.0033x over previous
#include <cuda_runtime.h>
#include <cuda_bf16.h>
#include <cstdint>

#define B_ 4
#define S_ 2048
#define DM_ 1024
#define H_ 16
#define DK_ 64
#define M_ (B_ * S_)   // 8192

// Scratch (device globals; allocation-free per harness rules)
__device__ __nv_bfloat16 g_Ahi[M_ * DM_];
__device__ __nv_bfloat16 g_Alo[M_ * DM_];
__device__ __nv_bfloat16 g_Whi[DM_ * DM_];
__device__ __nv_bfloat16 g_Wlo[DM_ * DM_];
__device__ __nv_bfloat16 g_Qhi[B_ * H_ * S_ * DK_];
__device__ __nv_bfloat16 g_Qlo[B_ * H_ * S_ * DK_];
__device__ __nv_bfloat16 g_Khi[B_ * H_ * S_ * DK_];
__device__ __nv_bfloat16 g_Klo[B_ * H_ * S_ * DK_];
__device__ __nv_bfloat16 g_Vhi[B_ * H_ * S_ * DK_];
__device__ __nv_bfloat16 g_Vlo[B_ * H_ * S_ * DK_];

// ===========================================================================
// Base-ISA helpers (valid on sm_103 WITHOUT the 'a' feature set)
// ===========================================================================
__device__ __forceinline__ uint32_t smem_u32(const void* p) {
    uint32_t a;
    asm("{ .reg .u64 t; cvta.to.shared.u64 t, %1; cvt.u32.u64 %0, t; }"
        : "=r"(a) : "l"(p));
    return a;
}
__device__ __forceinline__ void ldsm4(uint32_t* r, uint32_t addr) {
    asm volatile("ldmatrix.sync.aligned.m8n8.x4.shared.b16 {%0,%1,%2,%3}, [%4];"
                 : "=r"(r[0]), "=r"(r[1]), "=r"(r[2]), "=r"(r[3]) : "r"(addr));
}
__device__ __forceinline__ void ldsm4t(uint32_t* r, uint32_t addr) {
    asm volatile("ldmatrix.sync.aligned.m8n8.x4.trans.shared.b16 {%0,%1,%2,%3}, [%4];"
                 : "=r"(r[0]), "=r"(r[1]), "=r"(r[2]), "=r"(r[3]) : "r"(addr));
}
__device__ __forceinline__ void mma_bf16(float* d, const uint32_t* a, const uint32_t* b) {
    asm volatile(
        "mma.sync.aligned.m16n8k16.row.col.f32.bf16.bf16.f32 "
        "{%0,%1,%2,%3}, {%4,%5,%6,%7}, {%8,%9}, {%0,%1,%2,%3};"
        : "+f"(d[0]), "+f"(d[1]), "+f"(d[2]), "+f"(d[3])
        : "r"(a[0]), "r"(a[1]), "r"(a[2]), "r"(a[3]), "r"(b[0]), "r"(b[1]));
}
#define CP16(dst, src) \
    asm volatile("cp.async.cg.shared.global [%0], [%1], 16;" :: "r"(dst), "l"(src))
#define CP_COMMIT() asm volatile("cp.async.commit_group;" ::: "memory")
#define CP_WAIT0()  asm volatile("cp.async.wait_group 0;" ::: "memory")
#define CP_WAIT1()  asm volatile("cp.async.wait_group 1;" ::: "memory")

// split f32 pair -> bf16x2 hi + bf16x2 lo (packed u32)
__device__ __forceinline__ void split2(float a, float b, uint32_t& hi, uint32_t& lo) {
    __nv_bfloat162 h, l;
    h.x = __float2bfloat16(a); h.y = __float2bfloat16(b);
    l.x = __float2bfloat16(a - __bfloat162float(h.x));
    l.y = __float2bfloat16(b - __bfloat162float(h.y));
    hi = *reinterpret_cast<uint32_t*>(&h);
    lo = *reinterpret_cast<uint32_t*>(&l);
}

// ===========================================================================
// Pre-split: fp32 -> bf16 hi/lo pair
// ===========================================================================
__global__ __launch_bounds__(256) void split_kernel(
    const float* __restrict__ in,
    __nv_bfloat16* __restrict__ hi, __nv_bfloat16* __restrict__ lo)
{
    int i = blockIdx.x * blockDim.x + threadIdx.x;
    float4 v = reinterpret_cast<const float4*>(in)[i];
    uint32_t h0, h1, l0, l1;
    split2(v.x, v.y, h0, l0);
    split2(v.z, v.w, h1, l1);
    reinterpret_cast<uint32_t*>(hi)[i * 2 + 0] = h0;
    reinterpret_cast<uint32_t*>(hi)[i * 2 + 1] = h1;
    reinterpret_cast<uint32_t*>(lo)[i * 2 + 0] = l0;
    reinterpret_cast<uint32_t*>(lo)[i * 2 + 1] = l1;
}

// ===========================================================================
// bf16 HMMA GEMM: C[m,n] = sum_k A[m,k]*W[n,k] with 3-term hi/lo split.
// mode 0: Cf fp32 [m][1024].
// mode 1: Chi/Clo bf16 split, head layout [b,h,s,dk], scaled by `scale`.
// ===========================================================================
#define ROWB   80
#define TILEB  (128 * ROWB)
#define STAGEB (4 * TILEB)
#define SMEMG  (2 * STAGEB)      // 81920 B

__global__ __launch_bounds__(256, 2) void gemm_bf16_kernel(
    const __nv_bfloat16* __restrict__ Ahi, const __nv_bfloat16* __restrict__ Alo,
    const __nv_bfloat16* __restrict__ Bhi, const __nv_bfloat16* __restrict__ Blo,
    float* __restrict__ Cf,
    __nv_bfloat16* __restrict__ Chi, __nv_bfloat16* __restrict__ Clo,
    int mode, float scale)
{
    extern __shared__ char smg[];
    const uint32_t sbase = smem_u32(smg);
    const int tid  = threadIdx.x;
    const int lane = tid & 31;
    const int wid  = tid >> 5;
    const int wm   = (wid & 3) * 32;
    const int wn   = (wid >> 2) * 64;
    const int m0   = blockIdx.y * 128;
    const int n0   = blockIdx.x * 128;

    const __nv_bfloat16* gsrc[4] = {
        Ahi + (size_t)m0 * 1024, Alo + (size_t)m0 * 1024,
        Bhi + (size_t)n0 * 1024, Blo + (size_t)n0 * 1024 };

    float acc[2][8][4];
#pragma unroll
    for (int i = 0; i < 2; i++)
#pragma unroll
        for (int j = 0; j < 8; j++)
#pragma unroll
            for (int r = 0; r < 4; r++) acc[i][j][r] = 0.f;

    auto issue = [&](int c, int s) {
#pragma unroll
        for (int l = 0; l < 8; l++) {
            int T  = l >> 1;
            int q  = tid + (l & 1) * 256;
            int row = q >> 2, cc = q & 3;
            uint32_t dst = sbase + s * STAGEB + T * TILEB + row * ROWB + cc * 16;
            const __nv_bfloat16* src = gsrc[T] + (size_t)row * 1024 + c * 32 + cc * 8;
            CP16(dst, src);
        }
        CP_COMMIT();
    };

    issue(0, 0);

    const int a_roff = (lane & 7) + ((lane >> 3) & 1) * 8;
    const int a_coff = ((lane >> 4) & 1) * 16;
    const int b_roff = (lane & 7) + ((lane >> 4) & 1) * 8;
    const int b_coff = ((lane >> 3) & 1) * 16;

    for (int c = 0; c < 32; c++) {
        const int s = c & 1;
        CP_WAIT0();
        __syncthreads();
        if (c < 31) issue(c + 1, s ^ 1);

        const uint32_t tA_hi = sbase + s * STAGEB;
        const uint32_t tA_lo = tA_hi + TILEB;
        const uint32_t tB_hi = tA_hi + 2 * TILEB;
        const uint32_t tB_lo = tA_hi + 3 * TILEB;

#pragma unroll
        for (int ks = 0; ks < 2; ks++) {
            uint32_t ah[2][4], al[2][4];
#pragma unroll
            for (int mt = 0; mt < 2; mt++) {
                uint32_t off = (uint32_t)(wm + mt * 16 + a_roff) * ROWB + ks * 32 + a_coff;
                ldsm4(ah[mt], tA_hi + off);
                ldsm4(al[mt], tA_lo + off);
            }
#pragma unroll
            for (int np = 0; np < 4; np++) {
                uint32_t bh[4], bl[4];
                uint32_t off = (uint32_t)(wn + np * 16 + b_roff) * ROWB + ks * 32 + b_coff;
                ldsm4(bh, tB_hi + off);
                ldsm4(bl, tB_lo + off);
#pragma unroll
                for (int mt = 0; mt < 2; mt++) {
#pragma unroll
                    for (int j = 0; j < 2; j++) {
                        float* d = acc[mt][np * 2 + j];
                        mma_bf16(d, ah[mt], bh + j * 2);
                        mma_bf16(d, ah[mt], bl + j * 2);
                        mma_bf16(d, al[mt], bh + j * 2);
                    }
                }
            }
        }
        __syncthreads();
    }

#pragma unroll
    for (int mt = 0; mt < 2; mt++) {
#pragma unroll
        for (int nt = 0; nt < 8; nt++) {
            int row0 = m0 + wm + mt * 16 + (lane >> 2);
            int col  = n0 + wn + nt * 8 + (lane & 3) * 2;
            float2 v0 = make_float2(acc[mt][nt][0], acc[mt][nt][1]);
            float2 v1 = make_float2(acc[mt][nt][2], acc[mt][nt][3]);
            if (mode == 1) {
                int h = col >> 6, dk = col & 63;
#pragma unroll
                for (int rr = 0; rr < 2; rr++) {
                    int row = row0 + rr * 8;
                    float2 v = rr ? v1 : v0;
                    size_t idx = (((size_t)((row >> 11) * H_ + h) * S_) + (row & 2047)) * DK_ + dk;
                    uint32_t hi, lo;
                    split2(v.x * scale, v.y * scale, hi, lo);
                    *reinterpret_cast<uint32_t*>(Chi + idx) = hi;
                    *reinterpret_cast<uint32_t*>(Clo + idx) = lo;
                }
            } else {
                *reinterpret_cast<float2*>(&Cf[(size_t)row0 * 1024 + col]) = v0;
                *reinterpret_cast<float2*>(&Cf[(size_t)(row0 + 8) * 1024 + col]) = v1;
            }
        }
    }
}

// ===========================================================================
// Flash attention on HMMA, 3-term bf16 split.
// CTA: 128 q-rows x full key loop (64-key blocks). 8 warps, 16 q-rows each.
// Q/K: [row][dk] bf16 hi/lo (Q pre-scaled by 1/8). V natural [key][dk] via
// ldmatrix.trans. Output written as bf16 hi/lo split into Ahi/Alo [m][1024].
// ===========================================================================
#define AROW 144
#define QOFF 0              // 2 * 128*144 = 36864
#define KOFF 36864          // 2 bufs * 2 (hi/lo) * 64*144 = 36864
#define VOFF 73728
#define MOFF 110592         // 2 * 256
#define ASMEM 111104

__global__ __launch_bounds__(256, 2) void attn_mma_kernel(
    const __nv_bfloat16* __restrict__ Qhi, const __nv_bfloat16* __restrict__ Qlo,
    const __nv_bfloat16* __restrict__ Khi, const __nv_bfloat16* __restrict__ Klo,
    const __nv_bfloat16* __restrict__ Vhi, const __nv_bfloat16* __restrict__ Vlo,
    const int* __restrict__ mask,
    __nv_bfloat16* __restrict__ Ohi, __nv_bfloat16* __restrict__ Olo)
{
    extern __shared__ char sma[];
    const uint32_t sbase = smem_u32(sma);
    const int tid  = threadIdx.x;
    const int lane = tid & 31;
    const int wid  = tid >> 5;
    const int wq   = wid * 16;          // warp's q-row offset in CTA tile
    const int q0   = blockIdx.x * 128;
    const int h    = blockIdx.y;
    const int b    = blockIdx.z;

    const size_t bh = ((size_t)b * H_ + h) * S_ * DK_;
    const __nv_bfloat16* Qhi_b = Qhi + bh;
    const __nv_bfloat16* Qlo_b = Qlo + bh;
    const __nv_bfloat16* Khi_b = Khi + bh;
    const __nv_bfloat16* Klo_b = Klo + bh;
    const __nv_bfloat16* Vhi_b = Vhi + bh;
    const __nv_bfloat16* Vlo_b = Vlo + bh;
    const int* mrow = mask + b * S_;

    // ---- prologue: Q tile (once) + K/V/mask block 0 ----
#pragma unroll
    for (int i = 0; i < 8; i++) {
        int c = tid + i * 256;             // 0..2047
        int T = c >> 10;
        int idx = c & 1023;
        int row = idx >> 3, ch = idx & 7;
        uint32_t dst = sbase + QOFF + T * 18432 + row * AROW + ch * 16;
        const __nv_bfloat16* src = (T ? Qlo_b : Qhi_b) + (size_t)(q0 + row) * 64 + ch * 8;
        CP16(dst, src);
    }
    auto issueKV = [&](int kb, int s) {
#pragma unroll
        for (int i = 0; i < 4; i++) {
            int c = tid + i * 256;         // 0..1023
            int T = c >> 9;
            int idx = c & 511;
            int row = idx >> 3, ch = idx & 7;
            uint32_t doff = s * 9216 + T * 18432 + (uint32_t)row * AROW + ch * 16;
            size_t soff = (size_t)(kb * 64 + row) * 64 + ch * 8;
            CP16(sbase + KOFF + doff, (T ? Klo_b : Khi_b) + soff);
            CP16(sbase + VOFF + doff, (T ? Vlo_b : Vhi_b) + soff);
        }
        if (tid < 16)
            CP16(sbase + MOFF + s * 256 + tid * 16, mrow + kb * 64 + tid * 4);
    };
    issueKV(0, 0);
    CP_COMMIT();

    // fragment addressing
    const int a_roff  = (lane & 7) + ((lane >> 3) & 1) * 8;
    const int a_coff  = ((lane >> 4) & 1) * 16;
    const int b_roff  = (lane & 7) + ((lane >> 4) & 1) * 8;
    const int b_coff  = ((lane >> 3) & 1) * 16;
    const int vb_roff = (lane & 7) + ((lane >> 3) & 1) * 8;   // key within chunk
    const int vb_coff = ((lane >> 4) & 1) * 16;               // dk bytes

    float O[8][4];
#pragma unroll
    for (int i = 0; i < 8; i++)
#pragma unroll
        for (int j = 0; j < 4; j++) O[i][j] = 0.f;
    float mM[2] = {-1e30f, -1e30f};
    float lL[2] = {0.f, 0.f};

    for (int kb = 0; kb < 32; kb++) {
        const int s = kb & 1;
        if (kb < 31) { issueKV(kb + 1, s ^ 1); CP_COMMIT(); CP_WAIT1(); }
        else         { CP_WAIT0(); }
        __syncthreads();

        // ---- scores = Q @ K^T (pre-scaled) ----
        float sc[8][4];
#pragma unroll
        for (int i = 0; i < 8; i++)
#pragma unroll
            for (int j = 0; j < 4; j++) sc[i][j] = 0.f;

        const uint32_t kb_hi = sbase + KOFF + s * 9216;
        const uint32_t kb_lo = kb_hi + 18432;
#pragma unroll
        for (int ks = 0; ks < 4; ks++) {
            uint32_t ah[4], al[4];
            uint32_t aoff = (uint32_t)(wq + a_roff) * AROW + ks * 32 + a_coff;
            ldsm4(ah, sbase + QOFF + aoff);
            ldsm4(al, sbase + QOFF + 18432 + aoff);
#pragma unroll
            for (int np = 0; np < 4; np++) {
                uint32_t bh2[4], bl2[4];
                uint32_t boff = (uint32_t)(np * 16 + b_roff) * AROW + ks * 32 + b_coff;
                ldsm4(bh2, kb_hi + boff);
                ldsm4(bl2, kb_lo + boff);
#pragma unroll
                for (int j = 0; j < 2; j++) {
                    float* d = sc[np * 2 + j];
                    mma_bf16(d, ah, bh2 + j * 2);
                    mma_bf16(d, ah, bl2 + j * 2);
                    mma_bf16(d, al, bh2 + j * 2);
                }
            }
        }

        // ---- mask ----
        const int c0 = (lane & 3) * 2;
#pragma unroll
        for (int st = 0; st < 8; st++) {
            int2 mv = *reinterpret_cast<const int2*>(
                sma + (MOFF + s * 256) + (st * 8 + c0) * 4);
            if (mv.x == 0) { sc[st][0] = -1e9f; sc[st][2] = -1e9f; }
            if (mv.y == 0) { sc[st][1] = -1e9f; sc[st][3] = -1e9f; }
        }

        // ---- online softmax (2 rows per thread: r, r+8) ----
        float alpha[2];
#pragma unroll
        for (int rh = 0; rh < 2; rh++) {
            float mx = -1e30f;
#pragma unroll
            for (int st = 0; st < 8; st++)
                mx = fmaxf(mx, fmaxf(sc[st][rh * 2], sc[st][rh * 2 + 1]));
            mx = fmaxf(mx, __shfl_xor_sync(0xffffffffu, mx, 1));
            mx = fmaxf(mx, __shfl_xor_sync(0xffffffffu, mx, 2));
            float mn = fmaxf(mM[rh], mx);
            alpha[rh] = __expf(mM[rh] - mn);
            mM[rh] = mn;
            float rsum = 0.f;
#pragma unroll
            for (int st = 0; st < 8; st++) {
                float p0 = __expf(sc[st][rh * 2] - mn);
                float p1 = __expf(sc[st][rh * 2 + 1] - mn);
                sc[st][rh * 2] = p0; sc[st][rh * 2 + 1] = p1;
                rsum += p0 + p1;
            }
            rsum += __shfl_xor_sync(0xffffffffu, rsum, 1);
            rsum += __shfl_xor_sync(0xffffffffu, rsum, 2);
            lL[rh] = lL[rh] * alpha[rh] + rsum;
        }
#pragma unroll
        for (int nt = 0; nt < 8; nt++) {
            O[nt][0] *= alpha[0]; O[nt][1] *= alpha[0];
            O[nt][2] *= alpha[1]; O[nt][3] *= alpha[1];
        }

        // ---- O += P @ V (P from registers, V via ldmatrix.trans) ----
        const uint32_t vb_hi = sbase + VOFF + s * 9216;
        const uint32_t vb_lo = vb_hi + 18432;
#pragma unroll
        for (int ks = 0; ks < 4; ks++) {   // 16-key chunks
            uint32_t ph[4], pl[4];
            split2(sc[2 * ks][0],     sc[2 * ks][1],     ph[0], pl[0]);
            split2(sc[2 * ks][2],     sc[2 * ks][3],     ph[1], pl[1]);
            split2(sc[2 * ks + 1][0], sc[2 * ks + 1][1], ph[2], pl[2]);
            split2(sc[2 * ks + 1][2], sc[2 * ks + 1][3], ph[3], pl[3]);
#pragma unroll
            for (int np = 0; np < 4; np++) {  // 16-dk chunks
                uint32_t vh[4], vl[4];
                uint32_t voff = (uint32_t)(ks * 16 + vb_roff) * AROW + np * 32 + vb_coff;
                ldsm4t(vh, vb_hi + voff);
                ldsm4t(vl, vb_lo + voff);
#pragma unroll
                for (int j = 0; j < 2; j++) {
                    float* d = O[np * 2 + j];
                    mma_bf16(d, ph, vh + j * 2);
                    mma_bf16(d, ph, vl + j * 2);
                    mma_bf16(d, pl, vh + j * 2);
                }
            }
        }
        __syncthreads();
    }

    // ---- epilogue: O /= l, write bf16 hi/lo into [m][1024] ----
#pragma unroll
    for (int rh = 0; rh < 2; rh++) {
        float inv = 1.f / lL[rh];
        int row = q0 + wq + (lane >> 2) + rh * 8;
        size_t mrow_o = ((size_t)b * S_ + row) * DM_ + h * 64;
#pragma unroll
        for (int nt = 0; nt < 8; nt++) {
            int col = nt * 8 + (lane & 3) * 2;
            uint32_t hi, lo;
            split2(O[nt][rh * 2] * inv, O[nt][rh * 2 + 1] * inv, hi, lo);
            *reinterpret_cast<uint32_t*>(Ohi + mrow_o + col) = hi;
            *reinterpret_cast<uint32_t*>(Olo + mrow_o + col) = lo;
        }
    }
}

// ---------------------------------------------------------------------------
extern "C" void kernel_launch(void* const* d_in, const int* in_sizes, int n_in,
                              void* d_out, int out_size)
{
    const float* q    = (const float*)d_in[0];
    const float* k    = (const float*)d_in[1];
    const float* v    = (const float*)d_in[2];
    const int*   mask = (const int*)d_in[3];
    const float* Wq   = (const float*)d_in[4];
    const float* Wk   = (const float*)d_in[5];
    const float* Wv   = (const float*)d_in[6];
    const float* Wo   = (const float*)d_in[7];
    float* out = (float*)d_out;

    __nv_bfloat16 *ahi, *alo, *whi, *wlo, *qhi, *qlo, *khi, *klo, *vhi, *vlo;
    cudaGetSymbolAddress((void**)&ahi, g_Ahi);
    cudaGetSymbolAddress((void**)&alo, g_Alo);
    cudaGetSymbolAddress((void**)&whi, g_Whi);
    cudaGetSymbolAddress((void**)&wlo, g_Wlo);
    cudaGetSymbolAddress((void**)&qhi, g_Qhi);
    cudaGetSymbolAddress((void**)&qlo, g_Qlo);
    cudaGetSymbolAddress((void**)&khi, g_Khi);
    cudaGetSymbolAddress((void**)&klo, g_Klo);
    cudaGetSymbolAddress((void**)&vhi, g_Vhi);
    cudaGetSymbolAddress((void**)&vlo, g_Vlo);

    cudaFuncSetAttribute(gemm_bf16_kernel,
                         cudaFuncAttributeMaxDynamicSharedMemorySize, SMEMG);
    cudaFuncSetAttribute(attn_mma_kernel,
                         cudaFuncAttributeMaxDynamicSharedMemorySize, ASMEM);

    const int nA4 = M_ * DM_ / 4;
    const int nW4 = DM_ * DM_ / 4;
    dim3 gg(DM_ / 128, M_ / 128);

    // Q projection (pre-scale by 1/sqrt(dk) = 0.125)
    split_kernel<<<nA4 / 256, 256>>>(q, ahi, alo);
    split_kernel<<<nW4 / 256, 256>>>(Wq, whi, wlo);
    gemm_bf16_kernel<<<gg, 256, SMEMG>>>(ahi, alo, whi, wlo, nullptr, qhi, qlo, 1, 0.125f);
    // K projection
    split_kernel<<<nA4 / 256, 256>>>(k, ahi, alo);
    split_kernel<<<nW4 / 256, 256>>>(Wk, whi, wlo);
    gemm_bf16_kernel<<<gg, 256, SMEMG>>>(ahi, alo, whi, wlo, nullptr, khi, klo, 1, 1.0f);
    // V projection
    split_kernel<<<nA4 / 256, 256>>>(v, ahi, alo);
    split_kernel<<<nW4 / 256, 256>>>(Wv, whi, wlo);
    gemm_bf16_kernel<<<gg, 256, SMEMG>>>(ahi, alo, whi, wlo, nullptr, vhi, vlo, 1, 1.0f);

    // attention (writes bf16 hi/lo merged-head output into ahi/alo)
    attn_mma_kernel<<<dim3(S_ / 128, H_, B_), 256, ASMEM>>>(
        qhi, qlo, khi, klo, vhi, vlo, mask, ahi, alo);

    // output projection (fp32 result)
    split_kernel<<<nW4 / 256, 256>>>(Wo, whi, wlo);
    gemm_bf16_kernel<<<gg, 256, SMEMG>>>(ahi, alo, whi, wlo, out, nullptr, nullptr, 0, 1.0f);
}